// round 1
// baseline (speedup 1.0000x reference)
#include <cuda_runtime.h>
#include <cuda_bf16.h>
#include <math.h>

// Problem constants (fixed by this dataset instance)
#define Bsz 2
#define Sq  2048
#define Dm  1024
#define Hn  16
#define Dk  64
#define Mrows (Bsz*Sq)   // 4096

// ---------------- scratch (static device allocations are allowed) -----------
__device__ float g_Q[Bsz*Hn*Sq*Dk];   // [B,H,S,Dk]
__device__ float g_K[Bsz*Hn*Sq*Dk];
__device__ float g_V[Bsz*Hn*Sq*Dk];
__device__ float g_O[Bsz*Sq*Dm];      // [B,S,D] attention output (pre-Wo)

// ---------------- GEMM: C[m,n] = sum_k A[m,k] * W[n,k] ----------------------
// A: [M=4096, K=1024] row-major, W: [N=1024, K=1024] row-major.
// ROPE: apply rotary embedding on adjacent column pairs (dk = n%64).
// BHSD: write to [B,H,S,Dk] layout scratch; else plain [M,N] row-major.
#define GBM 128
#define GBN 64
#define GBK 16
#define GTM 8
#define GTN 4

template<bool ROPE, bool BHSD>
__global__ void __launch_bounds__(256)
gemm_xwt_kernel(const float* __restrict__ A, const float* __restrict__ W,
                float* __restrict__ C, const int* __restrict__ pos)
{
    __shared__ float As[GBK][GBM + 1];   // pitch 129 -> conflict-light
    __shared__ float Bs[GBK][GBN + 1];   // pitch 65

    const int tid = threadIdx.x;
    const int n0 = blockIdx.x * GBN;
    const int m0 = blockIdx.y * GBM;
    const int tn = (tid & 15) * GTN;
    const int tm = (tid >> 4) * GTM;

    float acc[GTM][GTN];
    #pragma unroll
    for (int i = 0; i < GTM; i++)
        #pragma unroll
        for (int j = 0; j < GTN; j++) acc[i][j] = 0.f;

    for (int k0 = 0; k0 < Dm; k0 += GBK) {
        // A tile: 128x16 = 2048 elems, 8 per thread
        #pragma unroll
        for (int u = 0; u < 8; u++) {
            int e = tid + u * 256;
            int r = e >> 4, c = e & 15;
            As[c][r] = A[(long)(m0 + r) * Dm + k0 + c];
        }
        // W tile: 64x16 = 1024 elems, 4 per thread
        #pragma unroll
        for (int u = 0; u < 4; u++) {
            int e = tid + u * 256;
            int r = e >> 4, c = e & 15;
            Bs[c][r] = W[(long)(n0 + r) * Dm + k0 + c];
        }
        __syncthreads();

        #pragma unroll
        for (int kk = 0; kk < GBK; kk++) {
            float rA[GTM], rB[GTN];
            #pragma unroll
            for (int i = 0; i < GTM; i++) rA[i] = As[kk][tm + i];
            #pragma unroll
            for (int j = 0; j < GTN; j++) rB[j] = Bs[kk][tn + j];
            #pragma unroll
            for (int i = 0; i < GTM; i++)
                #pragma unroll
                for (int j = 0; j < GTN; j++)
                    acc[i][j] = fmaf(rA[i], rB[j], acc[i][j]);
        }
        __syncthreads();
    }

    // epilogue
    #pragma unroll
    for (int i = 0; i < GTM; i++) {
        const int m = m0 + tm + i;
        const int b = m >> 11;        // /2048
        const int s = m & (Sq - 1);
        float p = 0.f;
        if (ROPE) p = (float)pos[m];
        #pragma unroll
        for (int j = 0; j < GTN; j += 2) {
            const int n = n0 + tn + j;     // even (tn multiple of 4)
            float e0 = acc[i][j], o0 = acc[i][j + 1];
            float re = e0, ro = o0;
            if (ROPE) {
                const int dk = n & (Dk - 1);              // even
                // theta^(-dk/Dk) = 2^(-dk/Dk * log2(theta))
                const float inv = exp2f((float)dk * (-13.2877123795494f / 64.0f)); // log2(10000)=13.28771...
                const float ang = p * inv;
                float sn, cs;
                sincosf(ang, &sn, &cs);   // accurate version: angles up to ~2047 rad
                re = e0 * cs - o0 * sn;
                ro = e0 * sn + o0 * cs;
            }
            if (BHSD) {
                const int h  = n >> 6;
                const int dk = n & (Dk - 1);
                long idx = (((long)(b * Hn + h) * Sq + s) * Dk + dk);
                C[idx]     = re;
                C[idx + 1] = ro;
            } else {
                long idx = (long)m * Dm + n;
                C[idx]     = re;
                C[idx + 1] = ro;
            }
        }
    }
}

// ---------------- causal flash attention, fp32, 1 query per thread ----------
// grid: (S/128, B*H), block: 128 threads. K/V tiles of 16 rows in smem.
__global__ void __launch_bounds__(128)
attn_kernel(const float* __restrict__ Q, const float* __restrict__ K,
            const float* __restrict__ V, float* __restrict__ O)
{
    __shared__ float Ks[16][Dk];
    __shared__ float Vs[16][Dk];

    const int bh  = blockIdx.y;            // b*H + h
    const int q0  = blockIdx.x * 128;
    const int tid = threadIdx.x;
    const int i   = q0 + tid;              // this thread's query index

    const float* __restrict__ Kbase = K + (long)bh * Sq * Dk;
    const float* __restrict__ Vbase = V + (long)bh * Sq * Dk;
    const float* __restrict__ Qrow  = Q + (long)bh * Sq * Dk + (long)i * Dk;

    float q[Dk];
    #pragma unroll
    for (int d = 0; d < Dk; d += 4) {
        float4 v = *reinterpret_cast<const float4*>(Qrow + d);
        q[d] = v.x; q[d+1] = v.y; q[d+2] = v.z; q[d+3] = v.w;
    }

    float acc[Dk];
    #pragma unroll
    for (int d = 0; d < Dk; d++) acc[d] = 0.f;
    float mi = -1e30f, li = 0.f;

    const float scale = 0.125f;            // 1/sqrt(64)
    const int ktiles = (q0 + 128) >> 4;    // causal: keys <= q0+127

    for (int kt = 0; kt < ktiles; kt++) {
        const int k0 = kt << 4;
        __syncthreads();
        // stage K/V tile: 16x64 floats = 256 float4, 2 per thread
        #pragma unroll
        for (int u = 0; u < 2; u++) {
            int e = tid + u * 128;
            int r = e >> 4;
            int c = (e & 15) << 2;
            *reinterpret_cast<float4*>(&Ks[r][c]) =
                *reinterpret_cast<const float4*>(Kbase + (long)(k0 + r) * Dk + c);
            *reinterpret_cast<float4*>(&Vs[r][c]) =
                *reinterpret_cast<const float4*>(Vbase + (long)(k0 + r) * Dk + c);
        }
        __syncthreads();

        if (k0 > i) continue;              // tile fully masked for this thread

        float s[16];
        #pragma unroll
        for (int jj = 0; jj < 16; jj++) {
            float dp = 0.f;
            #pragma unroll
            for (int d = 0; d < Dk; d++) dp = fmaf(q[d], Ks[jj][d], dp);
            s[jj] = (k0 + jj <= i) ? dp * scale : -1e30f;
        }
        float tmax = -1e30f;
        #pragma unroll
        for (int jj = 0; jj < 16; jj++) tmax = fmaxf(tmax, s[jj]);
        const float mnew = fmaxf(mi, tmax);
        const float corr = __expf(mi - mnew);
        li *= corr;
        #pragma unroll
        for (int d = 0; d < Dk; d++) acc[d] *= corr;
        #pragma unroll
        for (int jj = 0; jj < 16; jj++) {
            const float pj = __expf(s[jj] - mnew);
            li += pj;
            #pragma unroll
            for (int d = 0; d < Dk; d++) acc[d] = fmaf(pj, Vs[jj][d], acc[d]);
        }
        mi = mnew;
    }

    // write to [B,S,D] layout: row = b*S + i, cols h*64..h*64+63
    const int b = bh >> 4, h = bh & 15;
    const float inv = 1.0f / li;
    float* __restrict__ Orow = O + ((long)b * Sq + i) * Dm + h * Dk;
    #pragma unroll
    for (int d = 0; d < Dk; d += 4) {
        float4 v;
        v.x = acc[d] * inv; v.y = acc[d+1] * inv;
        v.z = acc[d+2] * inv; v.w = acc[d+3] * inv;
        *reinterpret_cast<float4*>(Orow + d) = v;
    }
}

// ---------------- launch --------------------------------------------------
extern "C" void kernel_launch(void* const* d_in, const int* in_sizes, int n_in,
                              void* d_out, int out_size)
{
    const float* x   = (const float*)d_in[0];
    const float* Wq  = (const float*)d_in[1];
    const float* Wk  = (const float*)d_in[2];
    const float* Wv  = (const float*)d_in[3];
    const float* Wo  = (const float*)d_in[4];
    const int*   pos = (const int*)d_in[5];
    float* out = (float*)d_out;

    float *Qp, *Kp, *Vp, *Op;
    cudaGetSymbolAddress((void**)&Qp, g_Q);
    cudaGetSymbolAddress((void**)&Kp, g_K);
    cudaGetSymbolAddress((void**)&Vp, g_V);
    cudaGetSymbolAddress((void**)&Op, g_O);

    dim3 ggrid(Dm / GBN, Mrows / GBM);   // (16, 32)
    gemm_xwt_kernel<true,  true ><<<ggrid, 256>>>(x,  Wq, Qp, pos);
    gemm_xwt_kernel<true,  true ><<<ggrid, 256>>>(x,  Wk, Kp, pos);
    gemm_xwt_kernel<false, true ><<<ggrid, 256>>>(x,  Wv, Vp, pos);

    dim3 agrid(Sq / 128, Bsz * Hn);      // (16, 32)
    attn_kernel<<<agrid, 128>>>(Qp, Kp, Vp, Op);

    gemm_xwt_kernel<false, false><<<ggrid, 256>>>(Op, Wo, out, pos);
}

// round 3
// speedup vs baseline: 1.3869x; 1.3869x over previous
#include <cuda_runtime.h>
#include <cuda_bf16.h>
#include <math.h>
#include <stdint.h>

// Problem constants (fixed by this dataset instance)
#define Bsz 2
#define Sq  2048
#define Dm  1024
#define Hn  16
#define Dk  64
#define Mrows (Bsz*Sq)   // 4096

// ---------------- scratch ----------------------------------------------------
__device__ float g_Q[Bsz*Hn*Sq*Dk];   // [B,H,S,Dk]
__device__ float g_K[Bsz*Hn*Sq*Dk];
__device__ float g_V[Bsz*Hn*Sq*Dk];
__device__ float g_O[Bsz*Sq*Dm];      // [B,S,D] attention output (pre-Wo)

// ================= small PTX wrappers (portable, compute_103-safe) ===========
__device__ __forceinline__ uint32_t smem_u32(const void* p) {
    uint32_t a;
    asm("{ .reg .u64 t; cvta.to.shared.u64 t, %1; cvt.u32.u64 %0, t; }"
        : "=r"(a) : "l"(p));
    return a;
}

__device__ __forceinline__ void ldsm_x4(uint32_t addr, uint32_t r[4]) {
    asm volatile("ldmatrix.sync.aligned.m8n8.x4.shared.b16 {%0,%1,%2,%3}, [%4];"
                 : "=r"(r[0]), "=r"(r[1]), "=r"(r[2]), "=r"(r[3]) : "r"(addr));
}
__device__ __forceinline__ void ldsm_x2(uint32_t addr, uint32_t r[2]) {
    asm volatile("ldmatrix.sync.aligned.m8n8.x2.shared.b16 {%0,%1}, [%2];"
                 : "=r"(r[0]), "=r"(r[1]) : "r"(addr));
}

__device__ __forceinline__ void mma_bf16(float c[4], const uint32_t a[4],
                                         const uint32_t b[2]) {
    asm volatile(
        "mma.sync.aligned.m16n8k16.row.col.f32.bf16.bf16.f32 "
        "{%0,%1,%2,%3}, {%4,%5,%6,%7}, {%8,%9}, {%0,%1,%2,%3};"
        : "+f"(c[0]), "+f"(c[1]), "+f"(c[2]), "+f"(c[3])
        : "r"(a[0]), "r"(a[1]), "r"(a[2]), "r"(a[3]), "r"(b[0]), "r"(b[1]));
}

__device__ __forceinline__ uint32_t pack_bf2(float x, float y) {
    __nv_bfloat162 t = __floats2bfloat162_rn(x, y);
    return *reinterpret_cast<uint32_t*>(&t);
}
__device__ __forceinline__ float bf_round(float x) {
    return __bfloat162float(__float2bfloat16(x));
}

// ================= tensor-core GEMM: C[m,n] = sum_k A[m,k]*W[n,k] ============
// bf16x3 compensated: D += Ahi*Bhi + Alo*Bhi + Ahi*Blo  (~fp32 accuracy)
#define BM 128
#define BN 128
#define BK 32
#define KT_ITERS (Dm/BK)          // 32
#define TPITCH 80                  // bytes per 32-bf16 row (conflict-free ldmatrix)
#define TILE_BYTES (128*TPITCH)    // 10240

template<bool ROPE, bool BHSD>
__global__ void __launch_bounds__(256, 1)
gemm_mma_kernel(const float* __restrict__ A, const float* __restrict__ W,
                float* __restrict__ C, const int* __restrict__ pos)
{
    __shared__ char sm[4 * TILE_BYTES];   // Ahi | Alo | Bhi | Blo
    char* tAhi = sm;
    char* tAlo = sm + TILE_BYTES;
    char* tBhi = sm + 2 * TILE_BYTES;
    char* tBlo = sm + 3 * TILE_BYTES;

    const int tid  = threadIdx.x;
    const int lane = tid & 31;
    const int wid  = tid >> 5;
    const int warp_m = wid & 1;        // 0..1 -> 64 rows each
    const int warp_n = wid >> 1;       // 0..3 -> 32 cols each
    const int n0 = blockIdx.x * BN;
    const int m0 = blockIdx.y * BM;

    float acc[4][4][4];
    #pragma unroll
    for (int i = 0; i < 4; i++)
        #pragma unroll
        for (int j = 0; j < 4; j++)
            #pragma unroll
            for (int v = 0; v < 4; v++) acc[i][j][v] = 0.f;

    // thread's producer slots: slot = tid + u*256 ; row = slot>>3, f4 = slot&7
    const int prow = tid >> 3;         // base row for u=0 (rows advance by 32 per u)
    const int pf4  = tid & 7;

    float4 pa[4], pb[4];
    #pragma unroll
    for (int u = 0; u < 4; u++) {
        const int r = prow + u * 32;
        pa[u] = *reinterpret_cast<const float4*>(A + (size_t)(m0 + r) * Dm + pf4 * 4);
        pb[u] = *reinterpret_cast<const float4*>(W + (size_t)(n0 + r) * Dm + pf4 * 4);
    }

    const uint32_t sAhi = smem_u32(tAhi);
    const uint32_t sAlo = smem_u32(tAlo);
    const uint32_t sBhi = smem_u32(tBhi);
    const uint32_t sBlo = smem_u32(tBlo);

    for (int kt = 0; kt < KT_ITERS; kt++) {
        // convert + store staged fp32 tiles as bf16 hi/lo
        #pragma unroll
        for (int u = 0; u < 4; u++) {
            const int r = prow + u * 32;
            const uint32_t off = (uint32_t)(r * TPITCH + pf4 * 8);
            {
                float4 v = pa[u];
                uint2 hi = make_uint2(pack_bf2(v.x, v.y), pack_bf2(v.z, v.w));
                float lx = v.x - bf_round(v.x), ly = v.y - bf_round(v.y);
                float lz = v.z - bf_round(v.z), lw = v.w - bf_round(v.w);
                uint2 lo = make_uint2(pack_bf2(lx, ly), pack_bf2(lz, lw));
                *reinterpret_cast<uint2*>(tAhi + off) = hi;
                *reinterpret_cast<uint2*>(tAlo + off) = lo;
            }
            {
                float4 v = pb[u];
                uint2 hi = make_uint2(pack_bf2(v.x, v.y), pack_bf2(v.z, v.w));
                float lx = v.x - bf_round(v.x), ly = v.y - bf_round(v.y);
                float lz = v.z - bf_round(v.z), lw = v.w - bf_round(v.w);
                uint2 lo = make_uint2(pack_bf2(lx, ly), pack_bf2(lz, lw));
                *reinterpret_cast<uint2*>(tBhi + off) = hi;
                *reinterpret_cast<uint2*>(tBlo + off) = lo;
            }
        }
        __syncthreads();

        // prefetch next k-tile (overlaps LDG latency with the MMAs below)
        if (kt + 1 < KT_ITERS) {
            const int kc = (kt + 1) * BK;
            #pragma unroll
            for (int u = 0; u < 4; u++) {
                const int r = prow + u * 32;
                pa[u] = *reinterpret_cast<const float4*>(A + (size_t)(m0 + r) * Dm + kc + pf4 * 4);
                pb[u] = *reinterpret_cast<const float4*>(W + (size_t)(n0 + r) * Dm + kc + pf4 * 4);
            }
        }

        // MMA over 2 k16 steps, 3 compensation passes
        #pragma unroll
        for (int ks = 0; ks < 2; ks++) {
            const int chunk = ks * 2;
            uint32_t ahi[4][4], alo[4][4], bhi[4][2], blo[4][2];
            #pragma unroll
            for (int mt = 0; mt < 4; mt++) {
                const int arow = warp_m * 64 + mt * 16 + (lane & 15);
                const uint32_t aoff = (uint32_t)(arow * TPITCH + (chunk + (lane >> 4)) * 16);
                ldsm_x4(sAhi + aoff, ahi[mt]);
                ldsm_x4(sAlo + aoff, alo[mt]);
            }
            #pragma unroll
            for (int nt = 0; nt < 4; nt++) {
                const int brow = warp_n * 32 + nt * 8 + (lane & 7);
                const uint32_t boff = (uint32_t)(brow * TPITCH + (chunk + ((lane >> 3) & 1)) * 16);
                ldsm_x2(sBhi + boff, bhi[nt]);
                ldsm_x2(sBlo + boff, blo[nt]);
            }
            #pragma unroll
            for (int mt = 0; mt < 4; mt++)
                #pragma unroll
                for (int nt = 0; nt < 4; nt++) {
                    mma_bf16(acc[mt][nt], ahi[mt], bhi[nt]);
                    mma_bf16(acc[mt][nt], alo[mt], bhi[nt]);
                    mma_bf16(acc[mt][nt], ahi[mt], blo[nt]);
                }
        }
        __syncthreads();
    }

    // ---- epilogue: fused RoPE + layout store ---------------------------------
    #pragma unroll
    for (int mt = 0; mt < 4; mt++) {
        #pragma unroll
        for (int half = 0; half < 2; half++) {
            const int row = m0 + warp_m * 64 + mt * 16 + (lane >> 2) + half * 8;
            const int b = row >> 11;
            const int s = row & (Sq - 1);
            float p = 0.f;
            if (ROPE) p = (float)pos[row];
            #pragma unroll
            for (int nt = 0; nt < 4; nt++) {
                const int col = n0 + warp_n * 32 + nt * 8 + (lane & 3) * 2;  // even
                float e = acc[mt][nt][half * 2];
                float o = acc[mt][nt][half * 2 + 1];
                if (ROPE) {
                    const int dk = col & (Dk - 1);
                    const float inv = exp2f((float)dk * (-13.287712379549449f / 64.0f));
                    float sn, cs;
                    sincosf(p * inv, &sn, &cs);
                    const float re = e * cs - o * sn;
                    const float ro = e * sn + o * cs;
                    e = re; o = ro;
                }
                if (BHSD) {
                    const int h  = col >> 6;
                    const int dk = col & (Dk - 1);
                    float* dst = C + (((size_t)(b * Hn + h) * Sq + s) * Dk + dk);
                    *reinterpret_cast<float2*>(dst) = make_float2(e, o);
                } else {
                    float* dst = C + (size_t)row * Dm + col;
                    *reinterpret_cast<float2*>(dst) = make_float2(e, o);
                }
            }
        }
    }
}

// ---------------- causal flash attention, fp32, 1 query per thread ----------
__global__ void __launch_bounds__(128)
attn_kernel(const float* __restrict__ Q, const float* __restrict__ K,
            const float* __restrict__ V, float* __restrict__ O)
{
    __shared__ float Ks[16][Dk];
    __shared__ float Vs[16][Dk];

    const int bh  = blockIdx.y;
    const int q0  = blockIdx.x * 128;
    const int tid = threadIdx.x;
    const int i   = q0 + tid;

    const float* __restrict__ Kbase = K + (size_t)bh * Sq * Dk;
    const float* __restrict__ Vbase = V + (size_t)bh * Sq * Dk;
    const float* __restrict__ Qrow  = Q + (size_t)bh * Sq * Dk + (size_t)i * Dk;

    float q[Dk];
    #pragma unroll
    for (int d = 0; d < Dk; d += 4) {
        float4 v = *reinterpret_cast<const float4*>(Qrow + d);
        q[d] = v.x; q[d+1] = v.y; q[d+2] = v.z; q[d+3] = v.w;
    }

    float acc[Dk];
    #pragma unroll
    for (int d = 0; d < Dk; d++) acc[d] = 0.f;
    float mi = -1e30f, li = 0.f;

    const float scale = 0.125f;
    const int ktiles = (q0 + 128) >> 4;

    for (int kt = 0; kt < ktiles; kt++) {
        const int k0 = kt << 4;
        __syncthreads();
        #pragma unroll
        for (int u = 0; u < 2; u++) {
            int e = tid + u * 128;
            int r = e >> 4;
            int c = (e & 15) << 2;
            *reinterpret_cast<float4*>(&Ks[r][c]) =
                *reinterpret_cast<const float4*>(Kbase + (size_t)(k0 + r) * Dk + c);
            *reinterpret_cast<float4*>(&Vs[r][c]) =
                *reinterpret_cast<const float4*>(Vbase + (size_t)(k0 + r) * Dk + c);
        }
        __syncthreads();

        if (k0 > i) continue;

        float s[16];
        #pragma unroll
        for (int jj = 0; jj < 16; jj++) {
            float dp = 0.f;
            #pragma unroll
            for (int d = 0; d < Dk; d++) dp = fmaf(q[d], Ks[jj][d], dp);
            s[jj] = (k0 + jj <= i) ? dp * scale : -1e30f;
        }
        float tmax = -1e30f;
        #pragma unroll
        for (int jj = 0; jj < 16; jj++) tmax = fmaxf(tmax, s[jj]);
        const float mnew = fmaxf(mi, tmax);
        const float corr = __expf(mi - mnew);
        li *= corr;
        #pragma unroll
        for (int d = 0; d < Dk; d++) acc[d] *= corr;
        #pragma unroll
        for (int jj = 0; jj < 16; jj++) {
            const float pj = __expf(s[jj] - mnew);
            li += pj;
            #pragma unroll
            for (int d = 0; d < Dk; d++) acc[d] = fmaf(pj, Vs[jj][d], acc[d]);
        }
        mi = mnew;
    }

    const int b = bh >> 4, h = bh & 15;
    const float inv = 1.0f / li;
    float* __restrict__ Orow = O + ((size_t)b * Sq + i) * Dm + h * Dk;
    #pragma unroll
    for (int d = 0; d < Dk; d += 4) {
        float4 v;
        v.x = acc[d] * inv; v.y = acc[d+1] * inv;
        v.z = acc[d+2] * inv; v.w = acc[d+3] * inv;
        *reinterpret_cast<float4*>(Orow + d) = v;
    }
}

// ---------------- launch -----------------------------------------------------
extern "C" void kernel_launch(void* const* d_in, const int* in_sizes, int n_in,
                              void* d_out, int out_size)
{
    const float* x   = (const float*)d_in[0];
    const float* Wq  = (const float*)d_in[1];
    const float* Wk  = (const float*)d_in[2];
    const float* Wv  = (const float*)d_in[3];
    const float* Wo  = (const float*)d_in[4];
    const int*   pos = (const int*)d_in[5];
    float* out = (float*)d_out;

    float *Qp, *Kp, *Vp, *Op;
    cudaGetSymbolAddress((void**)&Qp, g_Q);
    cudaGetSymbolAddress((void**)&Kp, g_K);
    cudaGetSymbolAddress((void**)&Vp, g_V);
    cudaGetSymbolAddress((void**)&Op, g_O);

    dim3 ggrid(Dm / BN, Mrows / BM);   // (8, 32)
    gemm_mma_kernel<true,  true ><<<ggrid, 256>>>(x,  Wq, Qp, pos);
    gemm_mma_kernel<true,  true ><<<ggrid, 256>>>(x,  Wk, Kp, pos);
    gemm_mma_kernel<false, true ><<<ggrid, 256>>>(x,  Wv, Vp, pos);

    dim3 agrid(Sq / 128, Bsz * Hn);    // (16, 32)
    attn_kernel<<<agrid, 128>>>(Qp, Kp, Vp, Op);

    gemm_mma_kernel<false, false><<<ggrid, 256>>>(Op, Wo, out, pos);
}